// round 13
// baseline (speedup 1.0000x reference)
#include <cuda_runtime.h>
#include <cuda_bf16.h>

// Problem constants (match reference)
#define N_ROWS     262144
#define NUM_CLS    80
#define CONF_TH    0.25f
#define K_ROWS     131072   // int(N * 0.5)

#define BLK          256
#define BLKS_PER_SM  8                       // 2048 threads/SM -> 100% occ cap
#define GRID_MAIN    (152 * BLKS_PER_SM)     // 1216 blocks, single resident wave
#define WARPS_TOTAL  (GRID_MAIN * (BLK / 32))// 9728 warps
#define ROW_BYTES    (NUM_CLS * 4)           // 320 B per row

// Device-global state (statically initialized; last block re-arms after
// producing the output -> identical initial state for every replay).
__device__ int    g_first_bad = K_ROWS;   // first row with max < CONF (K_ROWS if none)
__device__ double g_sum       = 0.0;      // optimistic sum of scores >= CONF
__device__ unsigned int g_done = 0;       // completed-block counter

// ---------------------------------------------------------------------------
// Single persistent kernel, warp-per-row-pair:
//   lanes 0..19 load rp[lane] (row 2g) and rp[lane+20] (row 2g+1) -> 640 B
//   contiguous per warp iteration, 8 live load regs/thread (~25 total) so
//   __launch_bounds__(256, 8) holds without spills (fixes R7's 50% occ cap).
// In-flight model: 64 warps/SM x 2 LDG.128 x 320 B = 40 KB/SM, vs ~16 KB
// needed to saturate the ~6300 B/cyc LTS ceiling -> MLP=2/warp suffices.
// Grid-stride over row pairs (~6.7 iterations/warp; fixes R7's imbalance).
// Per row (lane 0): atomicMin of first index with max < CONF; accumulate
// score if >= CONF. Rows < CONF never contribute to the reference answer
// (its loop breaks there), so this over-counts exactly the >=CONF rows past
// first_bad; the last block recomputes and subtracts those (empty in the
// common case first_bad == K_ROWS).
// ---------------------------------------------------------------------------
__global__ __launch_bounds__(BLK, BLKS_PER_SM)
void k_main(const float* __restrict__ pr, float* __restrict__ out) {
    __shared__ double swsum[BLK / 32];
    __shared__ bool   s_last;

    const int lane  = threadIdx.x & 31;
    const int wid   = threadIdx.x >> 5;
    const int gwarp = blockIdx.x * (BLK / 32) + wid;
    const bool active = lane < (NUM_CLS / 4);          // 20 float4 per row

    // byte-stride pointer walk: IADD per iteration instead of 64-bit IMAD
    const char* base = reinterpret_cast<const char*>(pr)
                     + (size_t)(gwarp * 2) * ROW_BYTES;
    const size_t step_bytes = (size_t)(WARPS_TOTAL * 2) * ROW_BYTES;

    float acc = 0.0f;                                   // lane-0 partial (<=14 rows)

    for (int row = gwarp * 2; row < K_ROWS; row += WARPS_TOTAL * 2, base += step_bytes) {
        const float4* rp = reinterpret_cast<const float4*>(base);

        float ma = -3.0e38f, mb = -3.0e38f;
        if (active) {
            float4 a = __ldg(&rp[lane]);                // row 2g
            float4 b = __ldg(&rp[lane + NUM_CLS / 4]);  // row 2g+1 (contiguous)
            ma = fmaxf(fmaxf(a.x, a.y), fmaxf(a.z, a.w));
            mb = fmaxf(fmaxf(b.x, b.y), fmaxf(b.z, b.w));
        }
        #pragma unroll
        for (int o = 16; o; o >>= 1) {
            ma = fmaxf(ma, __shfl_xor_sync(0xFFFFFFFFu, ma, o));
            mb = fmaxf(mb, __shfl_xor_sync(0xFFFFFFFFu, mb, o));
        }
        if (lane == 0) {
            if (ma < CONF_TH) atomicMin(&g_first_bad, row);
            else              acc += ma;
            if (mb < CONF_TH) atomicMin(&g_first_bad, row + 1);
            else              acc += mb;
        }
    }

    // block reduction of the optimistic sum (lane-0 values only)
    if (lane == 0) swsum[wid] = (double)acc;
    __syncthreads();

    if (threadIdx.x == 0) {
        double s = 0.0;
        #pragma unroll
        for (int i = 0; i < BLK / 32; i++) s += swsum[i];
        atomicAdd(&g_sum, s);
        __threadfence();                                // publish g_sum / g_first_bad
        unsigned int prev = atomicAdd(&g_done, 1u);
        s_last = (prev == GRID_MAIN - 1);
    }
    __syncthreads();
    if (!s_last) return;

    // ---- last block: correction + writeback + re-arm ----
    // Recompute maxima of rows >= first_bad from gmem (rare path; empty when
    // first_bad == K_ROWS). Warp-per-row, 8 rows per pass.
    const int fb = g_first_bad;
    double c = 0.0;
    for (int i = fb + wid; i < K_ROWS; i += BLK / 32) {
        const float4* rp = reinterpret_cast<const float4*>(pr + (size_t)i * NUM_CLS);
        float m = -3.0e38f;
        if (active) {
            float4 v = __ldg(&rp[lane]);
            m = fmaxf(fmaxf(v.x, v.y), fmaxf(v.z, v.w));
        }
        #pragma unroll
        for (int o = 16; o; o >>= 1)
            m = fmaxf(m, __shfl_xor_sync(0xFFFFFFFFu, m, o));
        if (lane == 0 && m >= CONF_TH) c += (double)m;  // over-counted rows
    }
    if (lane == 0) swsum[wid] = c;
    __syncthreads();

    if (threadIdx.x == 0) {
        double corr = 0.0;
        #pragma unroll
        for (int i = 0; i < BLK / 32; i++) corr += swsum[i];
        out[0] = (float)(g_sum - corr);
        // re-arm for the next (identical) invocation
        g_first_bad = K_ROWS;
        g_sum  = 0.0;
        g_done = 0u;
    }
}

extern "C" void kernel_launch(void* const* d_in, const int* in_sizes, int n_in,
                              void* d_out, int out_size) {
    const float* post_result = (const float*)d_in[0];
    float* out = (float*)d_out;

    k_main<<<GRID_MAIN, BLK>>>(post_result, out);
}